// round 14
// baseline (speedup 1.0000x reference)
#include <cuda_runtime.h>
#include <cuda_fp16.h>
#include <cstdint>

#define BB 4
#define TT 4096
#define EE 1024
#define HH 128
#define MTOT (BB*TT)

// scratch (device globals = allocation-free)
__device__ __align__(16) __half g_q[(size_t)MTOT*HH];       // Q fp16
__device__ __align__(16) __half g_k[(size_t)MTOT*HH];       // K fp16
__device__ __align__(16) __half g_v[(size_t)MTOT*HH];       // V fp16
__device__ __align__(16) __half g_wt[3*(size_t)HH*EE];      // W^T fp16, [p][h][e]

// ---------------------------------------------------------------------------
// helpers
// ---------------------------------------------------------------------------
__device__ __forceinline__ uint32_t smem_u32(const void* p) {
    uint32_t a;
    asm("{ .reg .u64 t; cvta.to.shared.u64 t, %1; cvt.u32.u64 %0, t; }" : "=r"(a) : "l"(p));
    return a;
}
__device__ __forceinline__ void ldsm4(uint32_t* r, uint32_t a) {
    asm volatile("ldmatrix.sync.aligned.m8n8.x4.shared.b16 {%0,%1,%2,%3}, [%4];"
        : "=r"(r[0]), "=r"(r[1]), "=r"(r[2]), "=r"(r[3]) : "r"(a));
}
__device__ __forceinline__ void ldsm4t(uint32_t* r, uint32_t a) {
    asm volatile("ldmatrix.sync.aligned.m8n8.x4.trans.shared.b16 {%0,%1,%2,%3}, [%4];"
        : "=r"(r[0]), "=r"(r[1]), "=r"(r[2]), "=r"(r[3]) : "r"(a));
}
__device__ __forceinline__ void mma16816h(float* c, const uint32_t* a, uint32_t b0, uint32_t b1) {
    asm volatile("mma.sync.aligned.m16n8k16.row.col.f32.f16.f16.f32 "
        "{%0,%1,%2,%3}, {%4,%5,%6,%7}, {%8,%9}, {%0,%1,%2,%3};"
        : "+f"(c[0]), "+f"(c[1]), "+f"(c[2]), "+f"(c[3])
        : "r"(a[0]), "r"(a[1]), "r"(a[2]), "r"(a[3]), "r"(b0), "r"(b1));
}
__device__ __forceinline__ uint32_t pack_half(float a, float b) {
    __half2 h = __floats2half2_rn(a, b);
    return *(uint32_t*)&h;
}
__device__ __forceinline__ float ex2(float x) {
    float r;
    asm("ex2.approx.ftz.f32 %0, %1;" : "=f"(r) : "f"(x));
    return r;
}
__device__ __forceinline__ void cp16(uint32_t saddr, const void* gptr) {
    asm volatile("cp.async.cg.shared.global [%0], [%1], 16;"
        :: "r"(saddr), "l"(__cvta_generic_to_global(gptr)) : "memory");
}
#define CP_COMMIT() asm volatile("cp.async.commit_group;" ::: "memory")
#define CP_WAIT0()  asm volatile("cp.async.wait_group 0;" ::: "memory")
#define BAR_GRP(id) asm volatile("bar.sync %0, 128;" :: "r"(id) : "memory")

// ---------------------------------------------------------------------------
// prep_w: W [E,H] -> Wt [H,E] fp16, via smem tile transpose (coalesced)
// ---------------------------------------------------------------------------
__global__ __launch_bounds__(256) void prep_w(
    const float* __restrict__ Wk, const float* __restrict__ Wq,
    const float* __restrict__ Wv)
{
    __shared__ float tile[32][129];
    const int p = blockIdx.y;
    const float* W = (p == 0) ? Wk : (p == 1) ? Wq : Wv;
    __half* ow = g_wt + (size_t)p * HH * EE;
    const int e0 = blockIdx.x * 32;

    #pragma unroll
    for (int i = 0; i < 16; i++) {
        int linear = i * 256 + threadIdx.x;
        int row = linear >> 7;
        int col = linear & 127;
        tile[row][col] = W[(size_t)(e0 + row) * HH + col];
    }
    __syncthreads();

    #pragma unroll
    for (int i = 0; i < 4; i++) {
        int linear = i * 256 + threadIdx.x;
        int h  = linear >> 3;
        int ec = linear & 7;
        __half h4[4];
        #pragma unroll
        for (int r = 0; r < 4; r++)
            h4[r] = __float2half_rn(tile[ec * 4 + r][h]);
        *(uint2*)&ow[(size_t)h * EE + e0 + ec * 4] = *(uint2*)h4;
    }
}

// ---------------------------------------------------------------------------
// proj_hmma: Y = X[16384,1024] @ W[1024,128], fp16 HMMA, BK=64 (16 k-iters).
// A32 staging SINGLE-buffered (each thread converts its own chunks before its
// own next-tile cp.async overwrites them; same-thread WAR is LSU-ordered).
// A16 + B double-buffered. Two barriers per iteration.
// ---------------------------------------------------------------------------
#define PA32 0                 // 128 rows x 272B (64 fp32 + pad) = 34816, single
#define PDB  34816             // double-buffered region base
#define PA16 0                 // within buffer: 128 rows x 144B = 18432
#define PB   18432             // within buffer: 128 rows x 144B = 18432
#define P_BUF 36864
#define PROJ_SMEM (34816 + 2*36864)   // 108544

__global__ __launch_bounds__(256, 2) void proj_hmma(
    const float* __restrict__ k_in, const float* __restrict__ q_in,
    const float* __restrict__ v_in)
{
    extern __shared__ char sm[];
    const uint32_t sbase = smem_u32(sm);
    const int t    = threadIdx.x;
    const int lane = t & 31;
    const int wid  = t >> 5;
    const int wm   = wid & 3;
    const int wn   = wid >> 2;
    const int p    = blockIdx.y;
    const int m0   = blockIdx.x * 128;

    const float* X = (p == 0) ? k_in : (p == 1) ? q_in : v_in;
    __half* Y = (p == 0) ? g_k : (p == 1) ? g_q : g_v;
    const __half* Wt = g_wt + (size_t)p * HH * EE;

    const uint32_t aoff = (uint32_t)((lane & 15) * 144 + (lane >> 4) * 16);
    const uint32_t boff = (uint32_t)((((lane & 7) | ((lane & 16) >> 1)) * 144) + (((lane >> 3) & 1) * 16));

    float acc[2][8][4];
    #pragma unroll
    for (int mb = 0; mb < 2; mb++)
        #pragma unroll
        for (int j = 0; j < 8; j++)
            #pragma unroll
            for (int i = 0; i < 4; i++) acc[mb][j][i] = 0.f;

    // async issue of tile kt: raw fp32 A into single A32, fp16 B into buffer
    auto issue_tile = [&](int kt, int buf) {
        uint32_t bbase = sbase + PDB + buf * P_BUF;
        #pragma unroll
        for (int i = 0; i < 8; i++) {       // A32: 128 rows x 16 chunks of 16B
            int linear = i * 256 + t;
            int c4  = linear & 15;
            int row = linear >> 4;
            cp16(sbase + PA32 + row * 272 + c4 * 16,
                 &X[(size_t)(m0 + row) * EE + kt * 64 + c4 * 4]);
        }
        #pragma unroll
        for (int i = 0; i < 4; i++) {       // B: 128 rows x 8 chunks of 16B
            int linear = i * 256 + t;
            int c8  = linear & 7;
            int row = linear >> 3;
            cp16(bbase + PB + row * 144 + c8 * 16,
                 &Wt[(size_t)row * EE + kt * 64 + c8 * 8]);
        }
        CP_COMMIT();
    };

    // convert A32 -> A16[buf]; each thread handles exactly the chunks it copied
    auto convert_tile = [&](int buf) {
        char* bbase = sm + PDB + buf * P_BUF;
        #pragma unroll
        for (int i = 0; i < 8; i++) {
            int linear = i * 256 + t;
            int c4  = linear & 15;
            int row = linear >> 4;
            float4 f = *(float4*)(sm + PA32 + row * 272 + c4 * 16);
            uint2 uh;
            uh.x = pack_half(f.x, f.y);
            uh.y = pack_half(f.z, f.w);
            *(uint2*)(bbase + PA16 + row * 144 + c4 * 8) = uh;
        }
    };

    issue_tile(0, 0);

    for (int kt = 0; kt < 16; kt++) {          // EE/64
        const int cur = kt & 1;
        const uint32_t sb = sbase + PDB + cur * P_BUF;
        CP_WAIT0();                 // own A32/B chunks of tile kt visible
        convert_tile(cur);          // own chunks only: no barrier needed
        if (kt < 15) issue_tile(kt + 1, cur ^ 1);  // A32 WAR is same-thread: safe
        __syncthreads();            // publish A16[cur]+B[cur]

        #pragma unroll
        for (int h = 0; h < 4; h++) {          // 4 k16 steps
            const uint32_t kb = h * 32;
            uint32_t ah[2][4];
            #pragma unroll
            for (int mb = 0; mb < 2; mb++) {
                uint32_t ra = (wm * 32 + mb * 16) * 144 + aoff + kb;
                ldsm4(ah[mb], sb + PA16 + ra);
            }
            #pragma unroll
            for (int jp = 0; jp < 4; jp++) {
                uint32_t b4[4];
                uint32_t rb = (wn * 64 + jp * 16) * 144 + boff + kb;
                ldsm4(b4, sb + PB + rb);
                #pragma unroll
                for (int mb = 0; mb < 2; mb++) {
                    mma16816h(acc[mb][2*jp],   ah[mb], b4[0], b4[1]);
                    mma16816h(acc[mb][2*jp+1], ah[mb], b4[2], b4[3]);
                }
            }
        }
        __syncthreads();            // all warps done reading buffers before reuse
    }

    const int g  = lane >> 2;
    const int q4 = lane & 3;
    #pragma unroll
    for (int mb = 0; mb < 2; mb++) {
        #pragma unroll
        for (int j = 0; j < 8; j++) {
            int gr  = m0 + wm * 32 + mb * 16 + g;
            int col = wn * 64 + j * 8 + q4 * 2;
            *(uint32_t*)&Y[(size_t)gr * HH + col] =
                pack_half(acc[mb][j][0], acc[mb][j][1]);
            *(uint32_t*)&Y[(size_t)(gr + 8) * HH + col] =
                pack_half(acc[mb][j][2], acc[mb][j][3]);
        }
    }
}

// ---------------------------------------------------------------------------
// flash_hmma: causal flash attention, fp16 MMA (unchanged from round 13).
// ---------------------------------------------------------------------------
#define FQ   0
#define FKV  17408          // + grp*34816
#define KBUF 0              // + par*8704
#define VBUF 17408          // + par*8704
#define FLASH_SMEM 87040

__global__ __launch_bounds__(256, 2) void flash_hmma(float* __restrict__ out)
{
    extern __shared__ char sm[];
    const uint32_t sbase = smem_u32(sm);
    const int t    = threadIdx.x;
    const int lane = t & 31;
    const int wid  = t >> 5;
    const int grp  = wid >> 2;
    const int wg   = wid & 3;
    const int gt   = t & 127;

    // SM-load-balanced bid -> (batch, qb): bid and bid+148 share an SM.
    int bid = blockIdx.x;
    int b, qb;
    if (bid >= 108 && bid < 148) {
        int s = bid - 108;
        qb = 63 - (s >> 2);
        b  = s & 3;
    } else {
        int r = (bid < 108) ? bid : (363 - bid);
        qb = 53 - (r >> 2);
        b  = r & 3;
    }

    const int q0   = qb * 64;
    const size_t bT = (size_t)b * TT;

    const uint32_t aoff = (uint32_t)((lane & 15) * 272 + (lane >> 4) * 16);
    const uint32_t boff = (uint32_t)((((lane & 7) | ((lane & 16) >> 1)) * 272) + (((lane >> 3) & 1) * 16));

    // ---- load Q tile (fp16, all 256 threads, cp.async) ----
    {
        const __half* qg = g_q + (bT + q0) * HH;
        #pragma unroll
        for (int i = 0; i < 4; i++) {
            int linear = i * 256 + t;
            int row = linear >> 4;
            int col = linear & 15;
            cp16(sbase + FQ + row * 272 + col * 16, &qg[(size_t)row * HH + col * 8]);
        }
        CP_COMMIT(); CP_WAIT0();
    }
    __syncthreads();

    float o[16][4];
    #pragma unroll
    for (int j = 0; j < 16; j++)
        #pragma unroll
        for (int i = 0; i < 4; i++) o[j][i] = 0.f;
    float m0 = -1e30f, m1 = -1e30f, l0 = 0.f, l1 = 0.f;

    const float scale_l2 = 0.088388347648318447f * 1.4426950408889634f;
    const int g   = lane >> 2;
    const int q4  = lane & 3;
    const int rg0 = q0 + wg * 16 + g;

    const uint32_t kvb = sbase + FKV + grp * 34816;
    const int nkb = 2 * qb + 2;
    const int barid = grp + 1;

    auto load_kv = [&](int kb, int par) {
        const size_t krow = bT + (size_t)kb * 32;
        uint32_t kd = kvb + KBUF + par * 8704;
        uint32_t vd = kvb + VBUF + par * 8704;
        #pragma unroll
        for (int i = 0; i < 4; i++) {
            int linear = i * 128 + gt;
            int row = linear >> 4;
            int col = linear & 15;
            uint32_t so = row * 272 + col * 16;
            size_t go = (krow + row) * HH + col * 8;
            cp16(kd + so, g_k + go);
            cp16(vd + so, g_v + go);
        }
    };

    if (grp < nkb) load_kv(grp, 0);
    CP_COMMIT();

    int par = 0;
    for (int kb = grp; kb < nkb; kb += 2, par ^= 1) {
        CP_WAIT0();
        BAR_GRP(barid);

        if (kb + 2 < nkb) load_kv(kb + 2, par ^ 1);
        CP_COMMIT();

        const uint32_t kcur = kvb + KBUF + par * 8704;
        const uint32_t vcur = kvb + VBUF + par * 8704;

        // ---- S = Q K^T (fp16), 32 KV cols ----
        float s[4][4];
        #pragma unroll
        for (int j = 0; j < 4; j++)
            #pragma unroll
            for (int i = 0; i < 4; i++) s[j][i] = 0.f;

        #pragma unroll
        for (int k16 = 0; k16 < 8; k16++) {
            uint32_t qa[4];
            uint32_t qr = wg * 16 * 272 + aoff + k16 * 32;
            ldsm4(qa, sbase + FQ + qr);
            #pragma unroll
            for (int jp = 0; jp < 2; jp++) {
                uint32_t k4[4];
                uint32_t kr = jp * 16 * 272 + boff + k16 * 32;
                ldsm4(k4, kcur + kr);
                mma16816h(s[2*jp],   qa, k4[0], k4[1]);
                mma16816h(s[2*jp+1], qa, k4[2], k4[3]);
            }
        }

        // ---- scale (log2 domain) + causal mask ----
        #pragma unroll
        for (int j = 0; j < 4; j++)
            #pragma unroll
            for (int i = 0; i < 4; i++) s[j][i] *= scale_l2;
        const int kv0 = kb * 32;
        if (kv0 + 31 > rg0) {
            int cbase = kv0 + q4 * 2;
            #pragma unroll
            for (int j = 0; j < 4; j++) {
                int c0 = cbase + j * 8;
                if (c0     > rg0)     s[j][0] = -1e30f;
                if (c0 + 1 > rg0)     s[j][1] = -1e30f;
                if (c0     > rg0 + 8) s[j][2] = -1e30f;
                if (c0 + 1 > rg0 + 8) s[j][3] = -1e30f;
            }
        }

        // ---- online softmax (rows g, g+8), exp2 domain ----
        float mx0 = -1e30f, mx1 = -1e30f;
        #pragma unroll
        for (int j = 0; j < 4; j++) {
            mx0 = fmaxf(mx0, fmaxf(s[j][0], s[j][1]));
            mx1 = fmaxf(mx1, fmaxf(s[j][2], s[j][3]));
        }
        mx0 = fmaxf(mx0, __shfl_xor_sync(0xffffffffu, mx0, 1));
        mx0 = fmaxf(mx0, __shfl_xor_sync(0xffffffffu, mx0, 2));
        mx1 = fmaxf(mx1, __shfl_xor_sync(0xffffffffu, mx1, 1));
        mx1 = fmaxf(mx1, __shfl_xor_sync(0xffffffffu, mx1, 2));
        float m0n = fmaxf(m0, mx0), m1n = fmaxf(m1, mx1);

        bool nochange = (m0n == m0) & (m1n == m1);
        bool skip = __all_sync(0xffffffffu, nochange);
        float a0 = 1.f, a1 = 1.f;
        if (!skip) {
            a0 = ex2(m0 - m0n);
            a1 = ex2(m1 - m1n);
            #pragma unroll
            for (int j = 0; j < 16; j++) {
                o[j][0] *= a0; o[j][1] *= a0;
                o[j][2] *= a1; o[j][3] *= a1;
            }
        }
        m0 = m0n; m1 = m1n;

        float esub0 = fmaxf(m0n, -1e20f);
        float esub1 = fmaxf(m1n, -1e20f);

        // P -> single fp16
        uint32_t ph01[4], ph23[4];
        float sum0 = 0.f, sum1 = 0.f;
        #pragma unroll
        for (int j = 0; j < 4; j++) {
            float p0 = ex2(s[j][0] - esub0);
            float p1 = ex2(s[j][1] - esub0);
            float p2 = ex2(s[j][2] - esub1);
            float p3 = ex2(s[j][3] - esub1);
            sum0 += p0 + p1; sum1 += p2 + p3;
            ph01[j] = pack_half(p0, p1);
            ph23[j] = pack_half(p2, p3);
        }
        sum0 += __shfl_xor_sync(0xffffffffu, sum0, 1);
        sum0 += __shfl_xor_sync(0xffffffffu, sum0, 2);
        sum1 += __shfl_xor_sync(0xffffffffu, sum1, 1);
        sum1 += __shfl_xor_sync(0xffffffffu, sum1, 2);
        l0 = l0 * a0 + sum0;
        l1 = l1 * a1 + sum1;

        // ---- O += P V (fp16) ----
        #pragma unroll
        for (int ks = 0; ks < 2; ks++) {
            uint32_t pa[4] = { ph01[2*ks], ph23[2*ks], ph01[2*ks+1], ph23[2*ks+1] };
            #pragma unroll
            for (int hp = 0; hp < 8; hp++) {
                uint32_t vh4[4];
                uint32_t vr = ks * 16 * 272 + aoff + hp * 32;
                ldsm4t(vh4, vcur + vr);
                mma16816h(o[2*hp],   pa, vh4[0], vh4[1]);
                mma16816h(o[2*hp+1], pa, vh4[2], vh4[3]);
            }
        }
    }

    // ---- merge group states (group1 -> smem -> group0) ----
    __syncthreads();
    float* mrg = (float*)(sm + FKV);
    const int slot = (wg * 32 + lane) * 69;
    if (grp == 1) {
        float* d = mrg + slot;
        #pragma unroll
        for (int j = 0; j < 16; j++) {
            d[j*4+0] = o[j][0]; d[j*4+1] = o[j][1];
            d[j*4+2] = o[j][2]; d[j*4+3] = o[j][3];
        }
        d[64] = m0; d[65] = m1; d[66] = l0; d[67] = l1;
    }
    __syncthreads();
    if (grp == 0) {
        const float* s2 = mrg + slot;
        float mB0 = s2[64], mB1 = s2[65], lB0 = s2[66], lB1 = s2[67];
        float mS0 = fmaxf(m0, mB0), mS1 = fmaxf(m1, mB1);
        float wA0 = ex2(m0 - mS0), wB0 = ex2(mB0 - mS0);
        float wA1 = ex2(m1 - mS1), wB1 = ex2(mB1 - mS1);
        float inv0 = 1.f / (l0 * wA0 + lB0 * wB0);
        float inv1 = 1.f / (l1 * wA1 + lB1 * wB1);
        #pragma unroll
        for (int j = 0; j < 16; j++) {
            int col = j * 8 + q4 * 2;
            float2 v0, v1;
            v0.x = (o[j][0] * wA0 + s2[j*4+0] * wB0) * inv0;
            v0.y = (o[j][1] * wA0 + s2[j*4+1] * wB0) * inv0;
            v1.x = (o[j][2] * wA1 + s2[j*4+2] * wB1) * inv1;
            v1.y = (o[j][3] * wA1 + s2[j*4+3] * wB1) * inv1;
            *(float2*)&out[(bT + rg0) * HH + col]     = v0;
            *(float2*)&out[(bT + rg0 + 8) * HH + col] = v1;
        }
    }
}

// ---------------------------------------------------------------------------
extern "C" void kernel_launch(void* const* d_in, const int* in_sizes, int n_in,
                              void* d_out, int out_size)
{
    const float* k  = (const float*)d_in[0];
    const float* q  = (const float*)d_in[1];
    const float* v  = (const float*)d_in[2];
    const float* Wk = (const float*)d_in[3];
    const float* Wq = (const float*)d_in[4];
    const float* Wv = (const float*)d_in[5];
    float* out = (float*)d_out;

    prep_w<<<dim3(EE / 32, 3), 256>>>(Wk, Wq, Wv);

    cudaFuncSetAttribute(proj_hmma, cudaFuncAttributeMaxDynamicSharedMemorySize, PROJ_SMEM);
    proj_hmma<<<dim3(MTOT / 128, 3), 256, PROJ_SMEM>>>(k, q, v);

    cudaFuncSetAttribute(flash_hmma, cudaFuncAttributeMaxDynamicSharedMemorySize, FLASH_SMEM);
    flash_hmma<<<256, 256, FLASH_SMEM>>>(out);
}

// round 15
// speedup vs baseline: 1.3714x; 1.3714x over previous
#include <cuda_runtime.h>
#include <cuda_fp16.h>
#include <cstdint>

#define BB 4
#define TT 4096
#define EE 1024
#define HH 128
#define MTOT (BB*TT)

// scratch (device globals = allocation-free)
__device__ __align__(16) __half g_q[(size_t)MTOT*HH];       // Q fp16
__device__ __align__(16) __half g_k[(size_t)MTOT*HH];       // K fp16
__device__ __align__(16) __half g_v[(size_t)MTOT*HH];       // V fp16
__device__ __align__(16) __half g_wt[3*(size_t)HH*EE];      // W^T fp16, [p][h][e]

// ---------------------------------------------------------------------------
// helpers
// ---------------------------------------------------------------------------
__device__ __forceinline__ uint32_t smem_u32(const void* p) {
    uint32_t a;
    asm("{ .reg .u64 t; cvta.to.shared.u64 t, %1; cvt.u32.u64 %0, t; }" : "=r"(a) : "l"(p));
    return a;
}
__device__ __forceinline__ void ldsm4(uint32_t* r, uint32_t a) {
    asm volatile("ldmatrix.sync.aligned.m8n8.x4.shared.b16 {%0,%1,%2,%3}, [%4];"
        : "=r"(r[0]), "=r"(r[1]), "=r"(r[2]), "=r"(r[3]) : "r"(a));
}
__device__ __forceinline__ void ldsm4t(uint32_t* r, uint32_t a) {
    asm volatile("ldmatrix.sync.aligned.m8n8.x4.trans.shared.b16 {%0,%1,%2,%3}, [%4];"
        : "=r"(r[0]), "=r"(r[1]), "=r"(r[2]), "=r"(r[3]) : "r"(a));
}
__device__ __forceinline__ void mma16816h(float* c, const uint32_t* a, uint32_t b0, uint32_t b1) {
    asm volatile("mma.sync.aligned.m16n8k16.row.col.f32.f16.f16.f32 "
        "{%0,%1,%2,%3}, {%4,%5,%6,%7}, {%8,%9}, {%0,%1,%2,%3};"
        : "+f"(c[0]), "+f"(c[1]), "+f"(c[2]), "+f"(c[3])
        : "r"(a[0]), "r"(a[1]), "r"(a[2]), "r"(a[3]), "r"(b0), "r"(b1));
}
__device__ __forceinline__ uint32_t pack_half(float a, float b) {
    __half2 h = __floats2half2_rn(a, b);
    return *(uint32_t*)&h;
}
__device__ __forceinline__ float ex2(float x) {
    float r;
    asm("ex2.approx.ftz.f32 %0, %1;" : "=f"(r) : "f"(x));
    return r;
}
__device__ __forceinline__ void cp16(uint32_t saddr, const void* gptr) {
    asm volatile("cp.async.cg.shared.global [%0], [%1], 16;"
        :: "r"(saddr), "l"(__cvta_generic_to_global(gptr)) : "memory");
}
#define CP_COMMIT() asm volatile("cp.async.commit_group;" ::: "memory")
#define CP_WAIT0()  asm volatile("cp.async.wait_group 0;" ::: "memory")
#define BAR_GRP(id) asm volatile("bar.sync %0, 128;" :: "r"(id) : "memory")

// ---------------------------------------------------------------------------
// prep_w: W [E,H] -> Wt [H,E] fp16, via smem tile transpose (coalesced)
// ---------------------------------------------------------------------------
__global__ __launch_bounds__(256) void prep_w(
    const float* __restrict__ Wk, const float* __restrict__ Wq,
    const float* __restrict__ Wv)
{
    __shared__ float tile[32][129];
    const int p = blockIdx.y;
    const float* W = (p == 0) ? Wk : (p == 1) ? Wq : Wv;
    __half* ow = g_wt + (size_t)p * HH * EE;
    const int e0 = blockIdx.x * 32;

    #pragma unroll
    for (int i = 0; i < 16; i++) {
        int linear = i * 256 + threadIdx.x;
        int row = linear >> 7;
        int col = linear & 127;
        tile[row][col] = W[(size_t)(e0 + row) * HH + col];
    }
    __syncthreads();

    #pragma unroll
    for (int i = 0; i < 4; i++) {
        int linear = i * 256 + threadIdx.x;
        int h  = linear >> 3;
        int ec = linear & 7;
        __half h4[4];
        #pragma unroll
        for (int r = 0; r < 4; r++)
            h4[r] = __float2half_rn(tile[ec * 4 + r][h]);
        *(uint2*)&ow[(size_t)h * EE + e0 + ec * 4] = *(uint2*)h4;
    }
}

// ---------------------------------------------------------------------------
// proj_hmma: Y = X[16384,1024] @ W[1024,128], fp16 HMMA, BK=32 (round-13
// layout, 2 CTAs/SM). SINGLE barrier per k-iter:
//   wait -> convert(cur) -> bar -> issue(next -> cur^1) -> mma(cur)
// Writes at iter kt touch only the buffer parity whose last readers were
// fenced by the PREVIOUS iteration's barrier.
// ---------------------------------------------------------------------------
#define PA32 0
#define PA16 18432
#define PB   28672
#define P_BUF 38912
#define PROJ_SMEM 77824

__global__ __launch_bounds__(256, 2) void proj_hmma(
    const float* __restrict__ k_in, const float* __restrict__ q_in,
    const float* __restrict__ v_in)
{
    extern __shared__ char sm[];
    const uint32_t sbase = smem_u32(sm);
    const int t    = threadIdx.x;
    const int lane = t & 31;
    const int wid  = t >> 5;
    const int wm   = wid & 3;
    const int wn   = wid >> 2;
    const int p    = blockIdx.y;
    const int m0   = blockIdx.x * 128;

    const float* X = (p == 0) ? k_in : (p == 1) ? q_in : v_in;
    __half* Y = (p == 0) ? g_k : (p == 1) ? g_q : g_v;
    const __half* Wt = g_wt + (size_t)p * HH * EE;

    const uint32_t aoff = (uint32_t)((lane & 15) * 80 + (lane >> 4) * 16);
    const uint32_t boff = (uint32_t)((((lane & 7) | ((lane & 16) >> 1)) * 80) + (((lane >> 3) & 1) * 16));

    float acc[2][8][4];
    #pragma unroll
    for (int mb = 0; mb < 2; mb++)
        #pragma unroll
        for (int j = 0; j < 8; j++)
            #pragma unroll
            for (int i = 0; i < 4; i++) acc[mb][j][i] = 0.f;

    // async issue of tile kt into buffer buf: raw fp32 A + fp16 B
    auto issue_tile = [&](int kt, int buf) {
        uint32_t ubase = sbase + buf * P_BUF;
        #pragma unroll
        for (int i = 0; i < 4; i++) {       // A32: 128 rows x 8 chunks of 16B
            int linear = i * 256 + t;
            int c4  = linear & 7;
            int row = linear >> 3;
            cp16(ubase + PA32 + row * 144 + c4 * 16,
                 &X[(size_t)(m0 + row) * EE + kt * 32 + c4 * 4]);
        }
        #pragma unroll
        for (int i = 0; i < 2; i++) {       // B: 128 rows x 4 chunks of 16B
            int linear = i * 256 + t;
            int c4  = linear & 3;
            int row = linear >> 2;
            cp16(ubase + PB + row * 80 + c4 * 16, &Wt[(size_t)row * EE + kt * 32 + c4 * 8]);
        }
        CP_COMMIT();
    };

    // convert A32[buf] -> A16[buf]; each thread handles the chunks it copied
    auto convert_tile = [&](int buf) {
        char* base = sm + buf * P_BUF;
        #pragma unroll
        for (int i = 0; i < 4; i++) {
            int linear = i * 256 + t;
            int c4  = linear & 7;
            int row = linear >> 3;
            float4 f = *(float4*)(base + PA32 + row * 144 + c4 * 16);
            uint2 uh;
            uh.x = pack_half(f.x, f.y);
            uh.y = pack_half(f.z, f.w);
            *(uint2*)(base + PA16 + row * 80 + c4 * 8) = uh;
        }
    };

    issue_tile(0, 0);

    for (int kt = 0; kt < 32; kt++) {
        const int cur = kt & 1;
        const uint32_t sb = sbase + cur * P_BUF;
        CP_WAIT0();                 // own chunks of tile kt visible to this thread
        convert_tile(cur);          // write A16[cur]: fenced by bar(kt-1)
        __syncthreads();            // publish tile kt; fence readers of cur^1
        if (kt < 31) issue_tile(kt + 1, cur ^ 1);   // safe: cur^1 readers fenced

        #pragma unroll
        for (int h = 0; h < 2; h++) {
            const uint32_t kb = h * 32;
            uint32_t ah[2][4];
            #pragma unroll
            for (int mb = 0; mb < 2; mb++) {
                uint32_t ra = (wm * 32 + mb * 16) * 80 + aoff + kb;
                ldsm4(ah[mb], sb + PA16 + ra);
            }
            #pragma unroll
            for (int jp = 0; jp < 4; jp++) {
                uint32_t b4[4];
                uint32_t rb = (wn * 64 + jp * 16) * 80 + boff + kb;
                ldsm4(b4, sb + PB + rb);
                #pragma unroll
                for (int mb = 0; mb < 2; mb++) {
                    mma16816h(acc[mb][2*jp],   ah[mb], b4[0], b4[1]);
                    mma16816h(acc[mb][2*jp+1], ah[mb], b4[2], b4[3]);
                }
            }
        }
    }

    const int g  = lane >> 2;
    const int q4 = lane & 3;
    #pragma unroll
    for (int mb = 0; mb < 2; mb++) {
        #pragma unroll
        for (int j = 0; j < 8; j++) {
            int gr  = m0 + wm * 32 + mb * 16 + g;
            int col = wn * 64 + j * 8 + q4 * 2;
            *(uint32_t*)&Y[(size_t)gr * HH + col] =
                pack_half(acc[mb][j][0], acc[mb][j][1]);
            *(uint32_t*)&Y[(size_t)(gr + 8) * HH + col] =
                pack_half(acc[mb][j][2], acc[mb][j][3]);
        }
    }
}

// ---------------------------------------------------------------------------
// flash_hmma: causal flash attention, fp16 MMA (unchanged from round 13).
// ---------------------------------------------------------------------------
#define FQ   0
#define FKV  17408          // + grp*34816
#define KBUF 0              // + par*8704
#define VBUF 17408          // + par*8704
#define FLASH_SMEM 87040

__global__ __launch_bounds__(256, 2) void flash_hmma(float* __restrict__ out)
{
    extern __shared__ char sm[];
    const uint32_t sbase = smem_u32(sm);
    const int t    = threadIdx.x;
    const int lane = t & 31;
    const int wid  = t >> 5;
    const int grp  = wid >> 2;
    const int wg   = wid & 3;
    const int gt   = t & 127;

    // SM-load-balanced bid -> (batch, qb): bid and bid+148 share an SM.
    int bid = blockIdx.x;
    int b, qb;
    if (bid >= 108 && bid < 148) {
        int s = bid - 108;
        qb = 63 - (s >> 2);
        b  = s & 3;
    } else {
        int r = (bid < 108) ? bid : (363 - bid);
        qb = 53 - (r >> 2);
        b  = r & 3;
    }

    const int q0   = qb * 64;
    const size_t bT = (size_t)b * TT;

    const uint32_t aoff = (uint32_t)((lane & 15) * 272 + (lane >> 4) * 16);
    const uint32_t boff = (uint32_t)((((lane & 7) | ((lane & 16) >> 1)) * 272) + (((lane >> 3) & 1) * 16));

    // ---- load Q tile (fp16, all 256 threads, cp.async) ----
    {
        const __half* qg = g_q + (bT + q0) * HH;
        #pragma unroll
        for (int i = 0; i < 4; i++) {
            int linear = i * 256 + t;
            int row = linear >> 4;
            int col = linear & 15;
            cp16(sbase + FQ + row * 272 + col * 16, &qg[(size_t)row * HH + col * 8]);
        }
        CP_COMMIT(); CP_WAIT0();
    }
    __syncthreads();

    float o[16][4];
    #pragma unroll
    for (int j = 0; j < 16; j++)
        #pragma unroll
        for (int i = 0; i < 4; i++) o[j][i] = 0.f;
    float m0 = -1e30f, m1 = -1e30f, l0 = 0.f, l1 = 0.f;

    const float scale_l2 = 0.088388347648318447f * 1.4426950408889634f;
    const int g   = lane >> 2;
    const int q4  = lane & 3;
    const int rg0 = q0 + wg * 16 + g;

    const uint32_t kvb = sbase + FKV + grp * 34816;
    const int nkb = 2 * qb + 2;
    const int barid = grp + 1;

    auto load_kv = [&](int kb, int par) {
        const size_t krow = bT + (size_t)kb * 32;
        uint32_t kd = kvb + KBUF + par * 8704;
        uint32_t vd = kvb + VBUF + par * 8704;
        #pragma unroll
        for (int i = 0; i < 4; i++) {
            int linear = i * 128 + gt;
            int row = linear >> 4;
            int col = linear & 15;
            uint32_t so = row * 272 + col * 16;
            size_t go = (krow + row) * HH + col * 8;
            cp16(kd + so, g_k + go);
            cp16(vd + so, g_v + go);
        }
    };

    if (grp < nkb) load_kv(grp, 0);
    CP_COMMIT();

    int par = 0;
    for (int kb = grp; kb < nkb; kb += 2, par ^= 1) {
        CP_WAIT0();
        BAR_GRP(barid);

        if (kb + 2 < nkb) load_kv(kb + 2, par ^ 1);
        CP_COMMIT();

        const uint32_t kcur = kvb + KBUF + par * 8704;
        const uint32_t vcur = kvb + VBUF + par * 8704;

        // ---- S = Q K^T (fp16), 32 KV cols ----
        float s[4][4];
        #pragma unroll
        for (int j = 0; j < 4; j++)
            #pragma unroll
            for (int i = 0; i < 4; i++) s[j][i] = 0.f;

        #pragma unroll
        for (int k16 = 0; k16 < 8; k16++) {
            uint32_t qa[4];
            uint32_t qr = wg * 16 * 272 + aoff + k16 * 32;
            ldsm4(qa, sbase + FQ + qr);
            #pragma unroll
            for (int jp = 0; jp < 2; jp++) {
                uint32_t k4[4];
                uint32_t kr = jp * 16 * 272 + boff + k16 * 32;
                ldsm4(k4, kcur + kr);
                mma16816h(s[2*jp],   qa, k4[0], k4[1]);
                mma16816h(s[2*jp+1], qa, k4[2], k4[3]);
            }
        }

        // ---- scale (log2 domain) + causal mask ----
        #pragma unroll
        for (int j = 0; j < 4; j++)
            #pragma unroll
            for (int i = 0; i < 4; i++) s[j][i] *= scale_l2;
        const int kv0 = kb * 32;
        if (kv0 + 31 > rg0) {
            int cbase = kv0 + q4 * 2;
            #pragma unroll
            for (int j = 0; j < 4; j++) {
                int c0 = cbase + j * 8;
                if (c0     > rg0)     s[j][0] = -1e30f;
                if (c0 + 1 > rg0)     s[j][1] = -1e30f;
                if (c0     > rg0 + 8) s[j][2] = -1e30f;
                if (c0 + 1 > rg0 + 8) s[j][3] = -1e30f;
            }
        }

        // ---- online softmax (rows g, g+8), exp2 domain ----
        float mx0 = -1e30f, mx1 = -1e30f;
        #pragma unroll
        for (int j = 0; j < 4; j++) {
            mx0 = fmaxf(mx0, fmaxf(s[j][0], s[j][1]));
            mx1 = fmaxf(mx1, fmaxf(s[j][2], s[j][3]));
        }
        mx0 = fmaxf(mx0, __shfl_xor_sync(0xffffffffu, mx0, 1));
        mx0 = fmaxf(mx0, __shfl_xor_sync(0xffffffffu, mx0, 2));
        mx1 = fmaxf(mx1, __shfl_xor_sync(0xffffffffu, mx1, 1));
        mx1 = fmaxf(mx1, __shfl_xor_sync(0xffffffffu, mx1, 2));
        float m0n = fmaxf(m0, mx0), m1n = fmaxf(m1, mx1);

        bool nochange = (m0n == m0) & (m1n == m1);
        bool skip = __all_sync(0xffffffffu, nochange);
        float a0 = 1.f, a1 = 1.f;
        if (!skip) {
            a0 = ex2(m0 - m0n);
            a1 = ex2(m1 - m1n);
            #pragma unroll
            for (int j = 0; j < 16; j++) {
                o[j][0] *= a0; o[j][1] *= a0;
                o[j][2] *= a1; o[j][3] *= a1;
            }
        }
        m0 = m0n; m1 = m1n;

        float esub0 = fmaxf(m0n, -1e20f);
        float esub1 = fmaxf(m1n, -1e20f);

        // P -> single fp16
        uint32_t ph01[4], ph23[4];
        float sum0 = 0.f, sum1 = 0.f;
        #pragma unroll
        for (int j = 0; j < 4; j++) {
            float p0 = ex2(s[j][0] - esub0);
            float p1 = ex2(s[j][1] - esub0);
            float p2 = ex2(s[j][2] - esub1);
            float p3 = ex2(s[j][3] - esub1);
            sum0 += p0 + p1; sum1 += p2 + p3;
            ph01[j] = pack_half(p0, p1);
            ph23[j] = pack_half(p2, p3);
        }
        sum0 += __shfl_xor_sync(0xffffffffu, sum0, 1);
        sum0 += __shfl_xor_sync(0xffffffffu, sum0, 2);
        sum1 += __shfl_xor_sync(0xffffffffu, sum1, 1);
        sum1 += __shfl_xor_sync(0xffffffffu, sum1, 2);
        l0 = l0 * a0 + sum0;
        l1 = l1 * a1 + sum1;

        // ---- O += P V (fp16) ----
        #pragma unroll
        for (int ks = 0; ks < 2; ks++) {
            uint32_t pa[4] = { ph01[2*ks], ph23[2*ks], ph01[2*ks+1], ph23[2*ks+1] };
            #pragma unroll
            for (int hp = 0; hp < 8; hp++) {
                uint32_t vh4[4];
                uint32_t vr = ks * 16 * 272 + aoff + hp * 32;
                ldsm4t(vh4, vcur + vr);
                mma16816h(o[2*hp],   pa, vh4[0], vh4[1]);
                mma16816h(o[2*hp+1], pa, vh4[2], vh4[3]);
            }
        }
    }

    // ---- merge group states (group1 -> smem -> group0) ----
    __syncthreads();
    float* mrg = (float*)(sm + FKV);
    const int slot = (wg * 32 + lane) * 69;
    if (grp == 1) {
        float* d = mrg + slot;
        #pragma unroll
        for (int j = 0; j < 16; j++) {
            d[j*4+0] = o[j][0]; d[j*4+1] = o[j][1];
            d[j*4+2] = o[j][2]; d[j*4+3] = o[j][3];
        }
        d[64] = m0; d[65] = m1; d[66] = l0; d[67] = l1;
    }
    __syncthreads();
    if (grp == 0) {
        const float* s2 = mrg + slot;
        float mB0 = s2[64], mB1 = s2[65], lB0 = s2[66], lB1 = s2[67];
        float mS0 = fmaxf(m0, mB0), mS1 = fmaxf(m1, mB1);
        float wA0 = ex2(m0 - mS0), wB0 = ex2(mB0 - mS0);
        float wA1 = ex2(m1 - mS1), wB1 = ex2(mB1 - mS1);
        float inv0 = 1.f / (l0 * wA0 + lB0 * wB0);
        float inv1 = 1.f / (l1 * wA1 + lB1 * wB1);
        #pragma unroll
        for (int j = 0; j < 16; j++) {
            int col = j * 8 + q4 * 2;
            float2 v0, v1;
            v0.x = (o[j][0] * wA0 + s2[j*4+0] * wB0) * inv0;
            v0.y = (o[j][1] * wA0 + s2[j*4+1] * wB0) * inv0;
            v1.x = (o[j][2] * wA1 + s2[j*4+2] * wB1) * inv1;
            v1.y = (o[j][3] * wA1 + s2[j*4+3] * wB1) * inv1;
            *(float2*)&out[(bT + rg0) * HH + col]     = v0;
            *(float2*)&out[(bT + rg0 + 8) * HH + col] = v1;
        }
    }
}

// ---------------------------------------------------------------------------
extern "C" void kernel_launch(void* const* d_in, const int* in_sizes, int n_in,
                              void* d_out, int out_size)
{
    const float* k  = (const float*)d_in[0];
    const float* q  = (const float*)d_in[1];
    const float* v  = (const float*)d_in[2];
    const float* Wk = (const float*)d_in[3];
    const float* Wq = (const float*)d_in[4];
    const float* Wv = (const float*)d_in[5];
    float* out = (float*)d_out;

    prep_w<<<dim3(EE / 32, 3), 256>>>(Wk, Wq, Wv);

    cudaFuncSetAttribute(proj_hmma, cudaFuncAttributeMaxDynamicSharedMemorySize, PROJ_SMEM);
    proj_hmma<<<dim3(MTOT / 128, 3), 256, PROJ_SMEM>>>(k, q, v);

    cudaFuncSetAttribute(flash_hmma, cudaFuncAttributeMaxDynamicSharedMemorySize, FLASH_SMEM);
    flash_hmma<<<256, 256, FLASH_SMEM>>>(out);
}

// round 16
// speedup vs baseline: 1.4385x; 1.0489x over previous
#include <cuda_runtime.h>
#include <cuda_fp16.h>
#include <cstdint>

#define BB 4
#define TT 4096
#define EE 1024
#define HH 128
#define MTOT (BB*TT)

// scratch (device globals = allocation-free)
__device__ __align__(16) __half g_q[(size_t)MTOT*HH];       // Q fp16
__device__ __align__(16) __half g_k[(size_t)MTOT*HH];       // K fp16
__device__ __align__(16) __half g_v[(size_t)MTOT*HH];       // V fp16
__device__ __align__(16) __half g_wt[3*(size_t)HH*EE];      // W^T fp16, [p][h][e]

// ---------------------------------------------------------------------------
// helpers
// ---------------------------------------------------------------------------
__device__ __forceinline__ uint32_t smem_u32(const void* p) {
    uint32_t a;
    asm("{ .reg .u64 t; cvta.to.shared.u64 t, %1; cvt.u32.u64 %0, t; }" : "=r"(a) : "l"(p));
    return a;
}
__device__ __forceinline__ void ldsm4(uint32_t* r, uint32_t a) {
    asm volatile("ldmatrix.sync.aligned.m8n8.x4.shared.b16 {%0,%1,%2,%3}, [%4];"
        : "=r"(r[0]), "=r"(r[1]), "=r"(r[2]), "=r"(r[3]) : "r"(a));
}
__device__ __forceinline__ void ldsm4t(uint32_t* r, uint32_t a) {
    asm volatile("ldmatrix.sync.aligned.m8n8.x4.trans.shared.b16 {%0,%1,%2,%3}, [%4];"
        : "=r"(r[0]), "=r"(r[1]), "=r"(r[2]), "=r"(r[3]) : "r"(a));
}
__device__ __forceinline__ void mma16816h(float* c, const uint32_t* a, uint32_t b0, uint32_t b1) {
    asm volatile("mma.sync.aligned.m16n8k16.row.col.f32.f16.f16.f32 "
        "{%0,%1,%2,%3}, {%4,%5,%6,%7}, {%8,%9}, {%0,%1,%2,%3};"
        : "+f"(c[0]), "+f"(c[1]), "+f"(c[2]), "+f"(c[3])
        : "r"(a[0]), "r"(a[1]), "r"(a[2]), "r"(a[3]), "r"(b0), "r"(b1));
}
__device__ __forceinline__ uint32_t pack_half(float a, float b) {
    __half2 h = __floats2half2_rn(a, b);
    return *(uint32_t*)&h;
}
__device__ __forceinline__ float ex2(float x) {
    float r;
    asm("ex2.approx.ftz.f32 %0, %1;" : "=f"(r) : "f"(x));
    return r;
}
__device__ __forceinline__ void cp16(uint32_t saddr, const void* gptr) {
    asm volatile("cp.async.cg.shared.global [%0], [%1], 16;"
        :: "r"(saddr), "l"(__cvta_generic_to_global(gptr)) : "memory");
}
#define CP_COMMIT() asm volatile("cp.async.commit_group;" ::: "memory")
#define CP_WAIT0()  asm volatile("cp.async.wait_group 0;" ::: "memory")
#define BAR_GRP(id) asm volatile("bar.sync %0, 128;" :: "r"(id) : "memory")

// ---------------------------------------------------------------------------
// prep_w: W [E,H] -> Wt [H,E] fp16, via smem tile transpose (coalesced)
// ---------------------------------------------------------------------------
__global__ __launch_bounds__(256) void prep_w(
    const float* __restrict__ Wk, const float* __restrict__ Wq,
    const float* __restrict__ Wv)
{
    __shared__ float tile[32][129];
    const int p = blockIdx.y;
    const float* W = (p == 0) ? Wk : (p == 1) ? Wq : Wv;
    __half* ow = g_wt + (size_t)p * HH * EE;
    const int e0 = blockIdx.x * 32;

    #pragma unroll
    for (int i = 0; i < 16; i++) {
        int linear = i * 256 + threadIdx.x;
        int row = linear >> 7;
        int col = linear & 127;
        tile[row][col] = W[(size_t)(e0 + row) * HH + col];
    }
    __syncthreads();

    #pragma unroll
    for (int i = 0; i < 4; i++) {
        int linear = i * 256 + threadIdx.x;
        int h  = linear >> 3;
        int ec = linear & 7;
        __half h4[4];
        #pragma unroll
        for (int r = 0; r < 4; r++)
            h4[r] = __float2half_rn(tile[ec * 4 + r][h]);
        *(uint2*)&ow[(size_t)h * EE + e0 + ec * 4] = *(uint2*)h4;
    }
}

// ---------------------------------------------------------------------------
// proj_hmma: EXACT round-13 structure (best measured):
//   wait -> convert(cur) -> issue(next) -> bar -> mma(cur) -> bar
// ---------------------------------------------------------------------------
#define PA32 0
#define PA16 18432
#define PB   28672
#define P_BUF 38912
#define PROJ_SMEM 77824

__global__ __launch_bounds__(256, 2) void proj_hmma(
    const float* __restrict__ k_in, const float* __restrict__ q_in,
    const float* __restrict__ v_in)
{
    extern __shared__ char sm[];
    const uint32_t sbase = smem_u32(sm);
    const int t    = threadIdx.x;
    const int lane = t & 31;
    const int wid  = t >> 5;
    const int wm   = wid & 3;
    const int wn   = wid >> 2;
    const int p    = blockIdx.y;
    const int m0   = blockIdx.x * 128;

    const float* X = (p == 0) ? k_in : (p == 1) ? q_in : v_in;
    __half* Y = (p == 0) ? g_k : (p == 1) ? g_q : g_v;
    const __half* Wt = g_wt + (size_t)p * HH * EE;

    const uint32_t aoff = (uint32_t)((lane & 15) * 80 + (lane >> 4) * 16);
    const uint32_t boff = (uint32_t)((((lane & 7) | ((lane & 16) >> 1)) * 80) + (((lane >> 3) & 1) * 16));

    float acc[2][8][4];
    #pragma unroll
    for (int mb = 0; mb < 2; mb++)
        #pragma unroll
        for (int j = 0; j < 8; j++)
            #pragma unroll
            for (int i = 0; i < 4; i++) acc[mb][j][i] = 0.f;

    auto issue_tile = [&](int kt, int buf) {
        uint32_t ubase = sbase + buf * P_BUF;
        #pragma unroll
        for (int i = 0; i < 4; i++) {       // A32: 128 rows x 8 chunks of 16B
            int linear = i * 256 + t;
            int c4  = linear & 7;
            int row = linear >> 3;
            cp16(ubase + PA32 + row * 144 + c4 * 16,
                 &X[(size_t)(m0 + row) * EE + kt * 32 + c4 * 4]);
        }
        #pragma unroll
        for (int i = 0; i < 2; i++) {       // B: 128 rows x 4 chunks of 16B
            int linear = i * 256 + t;
            int c4  = linear & 3;
            int row = linear >> 2;
            cp16(ubase + PB + row * 80 + c4 * 16, &Wt[(size_t)row * EE + kt * 32 + c4 * 8]);
        }
        CP_COMMIT();
    };

    auto convert_tile = [&](int buf) {
        char* base = sm + buf * P_BUF;
        #pragma unroll
        for (int i = 0; i < 4; i++) {
            int linear = i * 256 + t;
            int c4  = linear & 7;
            int row = linear >> 3;
            float4 f = *(float4*)(base + PA32 + row * 144 + c4 * 16);
            uint2 uh;
            uh.x = pack_half(f.x, f.y);
            uh.y = pack_half(f.z, f.w);
            *(uint2*)(base + PA16 + row * 80 + c4 * 8) = uh;
        }
    };

    issue_tile(0, 0);

    for (int kt = 0; kt < 32; kt++) {
        const int cur = kt & 1;
        const uint32_t sb = sbase + cur * P_BUF;
        CP_WAIT0();
        convert_tile(cur);
        if (kt < 31) issue_tile(kt + 1, cur ^ 1);
        __syncthreads();

        #pragma unroll
        for (int h = 0; h < 2; h++) {
            const uint32_t kb = h * 32;
            uint32_t ah[2][4];
            #pragma unroll
            for (int mb = 0; mb < 2; mb++) {
                uint32_t ra = (wm * 32 + mb * 16) * 80 + aoff + kb;
                ldsm4(ah[mb], sb + PA16 + ra);
            }
            #pragma unroll
            for (int jp = 0; jp < 4; jp++) {
                uint32_t b4[4];
                uint32_t rb = (wn * 64 + jp * 16) * 80 + boff + kb;
                ldsm4(b4, sb + PB + rb);
                #pragma unroll
                for (int mb = 0; mb < 2; mb++) {
                    mma16816h(acc[mb][2*jp],   ah[mb], b4[0], b4[1]);
                    mma16816h(acc[mb][2*jp+1], ah[mb], b4[2], b4[3]);
                }
            }
        }
        __syncthreads();
    }

    const int g  = lane >> 2;
    const int q4 = lane & 3;
    #pragma unroll
    for (int mb = 0; mb < 2; mb++) {
        #pragma unroll
        for (int j = 0; j < 8; j++) {
            int gr  = m0 + wm * 32 + mb * 16 + g;
            int col = wn * 64 + j * 8 + q4 * 2;
            *(uint32_t*)&Y[(size_t)gr * HH + col] =
                pack_half(acc[mb][j][0], acc[mb][j][1]);
            *(uint32_t*)&Y[(size_t)(gr + 8) * HH + col] =
                pack_half(acc[mb][j][2], acc[mb][j][3]);
        }
    }
}

// ---------------------------------------------------------------------------
// flash_hmma: causal flash attention, fp16 MMA.
// Q fragments hoisted into registers (loaded once) — no Q ldsm in the loop.
// ---------------------------------------------------------------------------
#define FQ   0
#define FKV  17408          // + grp*34816
#define KBUF 0              // + par*8704
#define VBUF 17408          // + par*8704
#define FLASH_SMEM 87040

__global__ __launch_bounds__(256, 2) void flash_hmma(float* __restrict__ out)
{
    extern __shared__ char sm[];
    const uint32_t sbase = smem_u32(sm);
    const int t    = threadIdx.x;
    const int lane = t & 31;
    const int wid  = t >> 5;
    const int grp  = wid >> 2;
    const int wg   = wid & 3;
    const int gt   = t & 127;

    // SM-load-balanced bid -> (batch, qb)
    int bid = blockIdx.x;
    int b, qb;
    if (bid >= 108 && bid < 148) {
        int s = bid - 108;
        qb = 63 - (s >> 2);
        b  = s & 3;
    } else {
        int r = (bid < 108) ? bid : (363 - bid);
        qb = 53 - (r >> 2);
        b  = r & 3;
    }

    const int q0   = qb * 64;
    const size_t bT = (size_t)b * TT;

    const uint32_t aoff = (uint32_t)((lane & 15) * 272 + (lane >> 4) * 16);
    const uint32_t boff = (uint32_t)((((lane & 7) | ((lane & 16) >> 1)) * 272) + (((lane >> 3) & 1) * 16));

    // ---- load Q tile, then hoist all 8 k16 fragments into registers ----
    {
        const __half* qg = g_q + (bT + q0) * HH;
        #pragma unroll
        for (int i = 0; i < 4; i++) {
            int linear = i * 256 + t;
            int row = linear >> 4;
            int col = linear & 15;
            cp16(sbase + FQ + row * 272 + col * 16, &qg[(size_t)row * HH + col * 8]);
        }
        CP_COMMIT(); CP_WAIT0();
    }
    __syncthreads();

    uint32_t qa[8][4];
    #pragma unroll
    for (int k16 = 0; k16 < 8; k16++) {
        uint32_t qr = wg * 16 * 272 + aoff + k16 * 32;
        ldsm4(qa[k16], sbase + FQ + qr);
    }

    float o[16][4];
    #pragma unroll
    for (int j = 0; j < 16; j++)
        #pragma unroll
        for (int i = 0; i < 4; i++) o[j][i] = 0.f;
    float m0 = -1e30f, m1 = -1e30f, l0 = 0.f, l1 = 0.f;

    const float scale_l2 = 0.088388347648318447f * 1.4426950408889634f;
    const int g   = lane >> 2;
    const int q4  = lane & 3;
    const int rg0 = q0 + wg * 16 + g;

    const uint32_t kvb = sbase + FKV + grp * 34816;
    const int nkb = 2 * qb + 2;
    const int barid = grp + 1;

    auto load_kv = [&](int kb, int par) {
        const size_t krow = bT + (size_t)kb * 32;
        uint32_t kd = kvb + KBUF + par * 8704;
        uint32_t vd = kvb + VBUF + par * 8704;
        #pragma unroll
        for (int i = 0; i < 4; i++) {
            int linear = i * 128 + gt;
            int row = linear >> 4;
            int col = linear & 15;
            uint32_t so = row * 272 + col * 16;
            size_t go = (krow + row) * HH + col * 8;
            cp16(kd + so, g_k + go);
            cp16(vd + so, g_v + go);
        }
    };

    if (grp < nkb) load_kv(grp, 0);
    CP_COMMIT();

    int par = 0;
    for (int kb = grp; kb < nkb; kb += 2, par ^= 1) {
        CP_WAIT0();
        BAR_GRP(barid);

        if (kb + 2 < nkb) load_kv(kb + 2, par ^ 1);
        CP_COMMIT();

        const uint32_t kcur = kvb + KBUF + par * 8704;
        const uint32_t vcur = kvb + VBUF + par * 8704;

        // ---- S = Q K^T (fp16), Q from registers ----
        float s[4][4];
        #pragma unroll
        for (int j = 0; j < 4; j++)
            #pragma unroll
            for (int i = 0; i < 4; i++) s[j][i] = 0.f;

        #pragma unroll
        for (int k16 = 0; k16 < 8; k16++) {
            #pragma unroll
            for (int jp = 0; jp < 2; jp++) {
                uint32_t k4[4];
                uint32_t kr = jp * 16 * 272 + boff + k16 * 32;
                ldsm4(k4, kcur + kr);
                mma16816h(s[2*jp],   qa[k16], k4[0], k4[1]);
                mma16816h(s[2*jp+1], qa[k16], k4[2], k4[3]);
            }
        }

        // ---- scale (log2 domain) + causal mask ----
        #pragma unroll
        for (int j = 0; j < 4; j++)
            #pragma unroll
            for (int i = 0; i < 4; i++) s[j][i] *= scale_l2;
        const int kv0 = kb * 32;
        if (kv0 + 31 > rg0) {
            int cbase = kv0 + q4 * 2;
            #pragma unroll
            for (int j = 0; j < 4; j++) {
                int c0 = cbase + j * 8;
                if (c0     > rg0)     s[j][0] = -1e30f;
                if (c0 + 1 > rg0)     s[j][1] = -1e30f;
                if (c0     > rg0 + 8) s[j][2] = -1e30f;
                if (c0 + 1 > rg0 + 8) s[j][3] = -1e30f;
            }
        }

        // ---- online softmax (rows g, g+8), exp2 domain ----
        float mx0 = -1e30f, mx1 = -1e30f;
        #pragma unroll
        for (int j = 0; j < 4; j++) {
            mx0 = fmaxf(mx0, fmaxf(s[j][0], s[j][1]));
            mx1 = fmaxf(mx1, fmaxf(s[j][2], s[j][3]));
        }
        mx0 = fmaxf(mx0, __shfl_xor_sync(0xffffffffu, mx0, 1));
        mx0 = fmaxf(mx0, __shfl_xor_sync(0xffffffffu, mx0, 2));
        mx1 = fmaxf(mx1, __shfl_xor_sync(0xffffffffu, mx1, 1));
        mx1 = fmaxf(mx1, __shfl_xor_sync(0xffffffffu, mx1, 2));
        float m0n = fmaxf(m0, mx0), m1n = fmaxf(m1, mx1);

        bool nochange = (m0n == m0) & (m1n == m1);
        bool skip = __all_sync(0xffffffffu, nochange);
        float a0 = 1.f, a1 = 1.f;
        if (!skip) {
            a0 = ex2(m0 - m0n);
            a1 = ex2(m1 - m1n);
            #pragma unroll
            for (int j = 0; j < 16; j++) {
                o[j][0] *= a0; o[j][1] *= a0;
                o[j][2] *= a1; o[j][3] *= a1;
            }
        }
        m0 = m0n; m1 = m1n;

        float esub0 = fmaxf(m0n, -1e20f);
        float esub1 = fmaxf(m1n, -1e20f);

        // P -> single fp16
        uint32_t ph01[4], ph23[4];
        float sum0 = 0.f, sum1 = 0.f;
        #pragma unroll
        for (int j = 0; j < 4; j++) {
            float p0 = ex2(s[j][0] - esub0);
            float p1 = ex2(s[j][1] - esub0);
            float p2 = ex2(s[j][2] - esub1);
            float p3 = ex2(s[j][3] - esub1);
            sum0 += p0 + p1; sum1 += p2 + p3;
            ph01[j] = pack_half(p0, p1);
            ph23[j] = pack_half(p2, p3);
        }
        sum0 += __shfl_xor_sync(0xffffffffu, sum0, 1);
        sum0 += __shfl_xor_sync(0xffffffffu, sum0, 2);
        sum1 += __shfl_xor_sync(0xffffffffu, sum1, 1);
        sum1 += __shfl_xor_sync(0xffffffffu, sum1, 2);
        l0 = l0 * a0 + sum0;
        l1 = l1 * a1 + sum1;

        // ---- O += P V (fp16) ----
        #pragma unroll
        for (int ks = 0; ks < 2; ks++) {
            uint32_t pa[4] = { ph01[2*ks], ph23[2*ks], ph01[2*ks+1], ph23[2*ks+1] };
            #pragma unroll
            for (int hp = 0; hp < 8; hp++) {
                uint32_t vh4[4];
                uint32_t vr = ks * 16 * 272 + aoff + hp * 32;
                ldsm4t(vh4, vcur + vr);
                mma16816h(o[2*hp],   pa, vh4[0], vh4[1]);
                mma16816h(o[2*hp+1], pa, vh4[2], vh4[3]);
            }
        }
    }

    // ---- merge group states (group1 -> smem -> group0) ----
    __syncthreads();
    float* mrg = (float*)(sm + FKV);
    const int slot = (wg * 32 + lane) * 69;
    if (grp == 1) {
        float* d = mrg + slot;
        #pragma unroll
        for (int j = 0; j < 16; j++) {
            d[j*4+0] = o[j][0]; d[j*4+1] = o[j][1];
            d[j*4+2] = o[j][2]; d[j*4+3] = o[j][3];
        }
        d[64] = m0; d[65] = m1; d[66] = l0; d[67] = l1;
    }
    __syncthreads();
    if (grp == 0) {
        const float* s2 = mrg + slot;
        float mB0 = s2[64], mB1 = s2[65], lB0 = s2[66], lB1 = s2[67];
        float mS0 = fmaxf(m0, mB0), mS1 = fmaxf(m1, mB1);
        float wA0 = ex2(m0 - mS0), wB0 = ex2(mB0 - mS0);
        float wA1 = ex2(m1 - mS1), wB1 = ex2(mB1 - mS1);
        float inv0 = 1.f / (l0 * wA0 + lB0 * wB0);
        float inv1 = 1.f / (l1 * wA1 + lB1 * wB1);
        #pragma unroll
        for (int j = 0; j < 16; j++) {
            int col = j * 8 + q4 * 2;
            float2 v0, v1;
            v0.x = (o[j][0] * wA0 + s2[j*4+0] * wB0) * inv0;
            v0.y = (o[j][1] * wA0 + s2[j*4+1] * wB0) * inv0;
            v1.x = (o[j][2] * wA1 + s2[j*4+2] * wB1) * inv1;
            v1.y = (o[j][3] * wA1 + s2[j*4+3] * wB1) * inv1;
            *(float2*)&out[(bT + rg0) * HH + col]     = v0;
            *(float2*)&out[(bT + rg0 + 8) * HH + col] = v1;
        }
    }
}

// ---------------------------------------------------------------------------
extern "C" void kernel_launch(void* const* d_in, const int* in_sizes, int n_in,
                              void* d_out, int out_size)
{
    const float* k  = (const float*)d_in[0];
    const float* q  = (const float*)d_in[1];
    const float* v  = (const float*)d_in[2];
    const float* Wk = (const float*)d_in[3];
    const float* Wq = (const float*)d_in[4];
    const float* Wv = (const float*)d_in[5];
    float* out = (float*)d_out;

    prep_w<<<dim3(EE / 32, 3), 256>>>(Wk, Wq, Wv);

    cudaFuncSetAttribute(proj_hmma, cudaFuncAttributeMaxDynamicSharedMemorySize, PROJ_SMEM);
    proj_hmma<<<dim3(MTOT / 128, 3), 256, PROJ_SMEM>>>(k, q, v);

    cudaFuncSetAttribute(flash_hmma, cudaFuncAttributeMaxDynamicSharedMemorySize, FLASH_SMEM);
    flash_hmma<<<256, 256, FLASH_SMEM>>>(out);
}